// round 2
// baseline (speedup 1.0000x reference)
#include <cuda_runtime.h>
#include <cstdint>
#include <cstddef>

// Problem constants
#define BB 2
#define HH 16
#define SS 2048
#define DD 2048
#define HD 128
#define QT 64              // q rows per block
#define KT 64              // kv rows per tile
#define NT (SS/KT)         // 32 tiles
#define NWARP 4

// Padded smem strides (in floats) chosen for conflict-free fragment loads
#define KSTR 132
#define VSTR 136
#define PSTR 68

#define SM_K (KT*KSTR)
#define SM_V (KT*VSTR)
#define SM_P (NWARP*16*PSTR)
#define SM_M KT
#define SMEM_FLOATS (SM_K + SM_V + SM_P + SM_M)
#define SMEM_BYTES (SMEM_FLOATS*4)

__device__ __forceinline__ unsigned f2tf(float x){
  unsigned r; asm("cvt.rna.tf32.f32 %0, %1;" : "=r"(r) : "f"(x)); return r;
}

__device__ __forceinline__ void mma8(float&c0,float&c1,float&c2,float&c3,
    unsigned a0,unsigned a1,unsigned a2,unsigned a3,unsigned b0,unsigned b1){
  asm volatile("mma.sync.aligned.m16n8k8.row.col.f32.tf32.tf32.f32 "
    "{%0,%1,%2,%3}, {%4,%5,%6,%7}, {%8,%9}, {%0,%1,%2,%3};"
    : "+f"(c0),"+f"(c1),"+f"(c2),"+f"(c3)
    : "r"(a0),"r"(a1),"r"(a2),"r"(a3),"r"(b0),"r"(b1));
}

// Load one 64x128 K tile into SMEM as tf32 with pair-permuted columns:
// element (r, k) stored at r*KSTR + (k&~7) + (k&3)*2 + ((k>>2)&1).
// This makes the mma B-fragment pair (k, k+4) contiguous -> single LDS.64.
__device__ __forceinline__ void load_k_tile(unsigned* KsmU, const float* Kb,
                                            int t, int tid){
  for (int ci = tid; ci < KT*16; ci += 128){
    int r  = ci >> 4;
    int cb = (ci & 15) * 8;
    const float* src = Kb + (size_t)(t*KT + r)*DD + cb;
    float4 lo = *(const float4*)src;
    float4 hi = *(const float4*)(src + 4);
    unsigned* d = KsmU + r*KSTR + cb;
    ((uint4*)d)[0] = make_uint4(f2tf(lo.x), f2tf(hi.x), f2tf(lo.y), f2tf(hi.y));
    ((uint4*)d)[1] = make_uint4(f2tf(lo.z), f2tf(hi.z), f2tf(lo.w), f2tf(hi.w));
  }
}

__global__ __launch_bounds__(128, 2)
void attn_fused(const float* __restrict__ Q, const float* __restrict__ K,
                const float* __restrict__ V, const float* __restrict__ Msk,
                float* __restrict__ O, float* __restrict__ W)
{
  extern __shared__ float smem[];
  float* Ksm = smem;
  float* Vsm = Ksm + SM_K;
  float* Psm = Vsm + SM_V;
  float* msm = Psm + SM_P;
  unsigned* KsmU = (unsigned*)Ksm;
  unsigned* VsmU = (unsigned*)Vsm;

  const int tid  = threadIdx.x;
  const int warp = tid >> 5, lane = tid & 31;
  const int g = lane >> 2, q4 = lane & 3;
  const int b = blockIdx.z, h = blockIdx.y, qt = blockIdx.x;
  const int q0 = qt*QT + warp*16;

  const float* Qb = Q + ((size_t)b*SS)*DD + (size_t)h*HD;
  const float* Kb = K + ((size_t)b*SS)*DD + (size_t)h*HD;
  const float* Vb = V + ((size_t)b*SS)*DD + (size_t)h*HD;
  const float* Mb = Msk + (size_t)b*SS;

  const float scale = 0.08838834764831845f;  // 1/sqrt(128)

  // Q fragments cached in registers (tf32), rows q0+g and q0+g+8
  unsigned qr[16][4];
  {
    const float* r0 = Qb + (size_t)(q0+g)*DD;
    const float* r1 = Qb + (size_t)(q0+g+8)*DD;
#pragma unroll
    for (int kk=0; kk<16; kk++){
      qr[kk][0] = f2tf(r0[kk*8 + q4]);
      qr[kk][1] = f2tf(r1[kk*8 + q4]);
      qr[kk][2] = f2tf(r0[kk*8 + 4 + q4]);
      qr[kk][3] = f2tf(r1[kk*8 + 4 + q4]);
    }
  }

  float m0=-1e30f, m1=-1e30f, l0=0.f, l1=0.f;

  // ---------------- pass A: softmax row stats (online max / sumexp) ----------------
  for (int t=0; t<NT; t++){
    __syncthreads();
    load_k_tile(KsmU, Kb, t, tid);
    if (tid < KT) msm[tid] = Mb[t*KT + tid];
    __syncthreads();

    float s[8][4];
#pragma unroll
    for (int j=0;j<8;j++){ s[j][0]=0.f;s[j][1]=0.f;s[j][2]=0.f;s[j][3]=0.f; }
#pragma unroll
    for (int kk=0; kk<16; kk++){
#pragma unroll
      for (int j=0;j<8;j++){
        uint2 bb = *(const uint2*)(KsmU + (j*8+g)*KSTR + kk*8 + q4*2);
        mma8(s[j][0],s[j][1],s[j][2],s[j][3],
             qr[kk][0],qr[kk][1],qr[kk][2],qr[kk][3], bb.x, bb.y);
      }
    }
    float tm0=-1e30f, tm1=-1e30f;
#pragma unroll
    for (int j=0;j<8;j++){
      float mk0 = msm[j*8 + 2*q4], mk1 = msm[j*8 + 2*q4 + 1];
      s[j][0] = fmaf(s[j][0], scale, mk0);
      s[j][1] = fmaf(s[j][1], scale, mk1);
      s[j][2] = fmaf(s[j][2], scale, mk0);
      s[j][3] = fmaf(s[j][3], scale, mk1);
      tm0 = fmaxf(tm0, fmaxf(s[j][0], s[j][1]));
      tm1 = fmaxf(tm1, fmaxf(s[j][2], s[j][3]));
    }
    tm0 = fmaxf(tm0, __shfl_xor_sync(0xffffffffu, tm0, 1));
    tm0 = fmaxf(tm0, __shfl_xor_sync(0xffffffffu, tm0, 2));
    tm1 = fmaxf(tm1, __shfl_xor_sync(0xffffffffu, tm1, 1));
    tm1 = fmaxf(tm1, __shfl_xor_sync(0xffffffffu, tm1, 2));
    float nm0 = fmaxf(m0, tm0), nm1 = fmaxf(m1, tm1);
    float sm0=0.f, sm1=0.f;
#pragma unroll
    for (int j=0;j<8;j++){
      sm0 += __expf(s[j][0]-nm0) + __expf(s[j][1]-nm0);
      sm1 += __expf(s[j][2]-nm1) + __expf(s[j][3]-nm1);
    }
    sm0 += __shfl_xor_sync(0xffffffffu, sm0, 1);
    sm0 += __shfl_xor_sync(0xffffffffu, sm0, 2);
    sm1 += __shfl_xor_sync(0xffffffffu, sm1, 1);
    sm1 += __shfl_xor_sync(0xffffffffu, sm1, 2);
    l0 = l0*__expf(m0-nm0) + sm0;
    l1 = l1*__expf(m1-nm1) + sm1;
    m0 = nm0; m1 = nm1;
  }
  const float il0 = 1.f/l0, il1 = 1.f/l1;

  // ---------------- pass B: recompute scores, emit weights, PV ----------------
  float o[16][4];
#pragma unroll
  for (int j=0;j<16;j++){ o[j][0]=0.f;o[j][1]=0.f;o[j][2]=0.f;o[j][3]=0.f; }

  float* wr0 = W + (((size_t)(b*HH+h))*SS + (size_t)(q0+g))*SS;
  float* wr1 = W + (((size_t)(b*HH+h))*SS + (size_t)(q0+g+8))*SS;
  unsigned* pw = (unsigned*)Psm + warp*16*PSTR;

  for (int t=0; t<NT; t++){
    __syncthreads();
    load_k_tile(KsmU, Kb, t, tid);
    // V tile, plain layout, tf32
    for (int i=tid; i<KT*32; i+=128){
      int r = i>>5, c = (i&31)*4;
      float4 v = *(const float4*)(Vb + (size_t)(t*KT + r)*DD + c);
      ((uint4*)(VsmU + r*VSTR + c))[0] =
          make_uint4(f2tf(v.x), f2tf(v.y), f2tf(v.z), f2tf(v.w));
    }
    if (tid < KT) msm[tid] = Mb[t*KT + tid];
    __syncthreads();

    float s[8][4];
#pragma unroll
    for (int j=0;j<8;j++){ s[j][0]=0.f;s[j][1]=0.f;s[j][2]=0.f;s[j][3]=0.f; }
#pragma unroll
    for (int kk=0; kk<16; kk++){
#pragma unroll
      for (int j=0;j<8;j++){
        uint2 bb = *(const uint2*)(KsmU + (j*8+g)*KSTR + kk*8 + q4*2);
        mma8(s[j][0],s[j][1],s[j][2],s[j][3],
             qr[kk][0],qr[kk][1],qr[kk][2],qr[kk][3], bb.x, bb.y);
      }
    }

#pragma unroll
    for (int j=0;j<8;j++){
      float mk0 = msm[j*8 + 2*q4], mk1 = msm[j*8 + 2*q4 + 1];
      float p0 = __expf(fmaf(s[j][0], scale, mk0) - m0) * il0;
      float p1 = __expf(fmaf(s[j][1], scale, mk1) - m0) * il0;
      float p2 = __expf(fmaf(s[j][2], scale, mk0) - m1) * il1;
      float p3 = __expf(fmaf(s[j][3], scale, mk1) - m1) * il1;
      int col = j*8 + 2*q4;
      *(float2*)(wr0 + (size_t)t*KT + col) = make_float2(p0, p1);
      *(float2*)(wr1 + (size_t)t*KT + col) = make_float2(p2, p3);
      pw[g*PSTR + col]       = f2tf(p0);
      pw[g*PSTR + col + 1]   = f2tf(p1);
      pw[(g+8)*PSTR + col]   = f2tf(p2);
      pw[(g+8)*PSTR + col+1] = f2tf(p3);
    }
    __syncwarp();

    // PV: O(16x128) += P(16x64) @ V(64x128)
#pragma unroll
    for (int kk=0; kk<8; kk++){
      unsigned a0 = pw[g*PSTR     + kk*8 + q4];
      unsigned a1 = pw[(g+8)*PSTR + kk*8 + q4];
      unsigned a2 = pw[g*PSTR     + kk*8 + 4 + q4];
      unsigned a3 = pw[(g+8)*PSTR + kk*8 + 4 + q4];
#pragma unroll
      for (int j=0;j<16;j++){
        unsigned b0 = VsmU[(kk*8 + q4)*VSTR     + j*8 + g];
        unsigned b1 = VsmU[(kk*8 + 4 + q4)*VSTR + j*8 + g];
        mma8(o[j][0],o[j][1],o[j][2],o[j][3], a0,a1,a2,a3, b0,b1);
      }
    }
  }

  // epilogue: write attn_output [B, S, D] with head h at columns h*HD
  float* or0 = O + ((size_t)b*SS + (size_t)(q0+g))*DD + (size_t)h*HD;
  float* or1 = O + ((size_t)b*SS + (size_t)(q0+g+8))*DD + (size_t)h*HD;
#pragma unroll
  for (int j=0;j<16;j++){
    int col = j*8 + 2*q4;
    *(float2*)(or0 + col) = make_float2(o[j][0], o[j][1]);
    *(float2*)(or1 + col) = make_float2(o[j][2], o[j][3]);
  }
}

extern "C" void kernel_launch(void* const* d_in, const int* in_sizes, int n_in,
                              void* d_out, int out_size) {
  const float* Q = (const float*)d_in[0];
  const float* K = (const float*)d_in[1];
  const float* V = (const float*)d_in[2];
  const float* M = (const float*)d_in[3];
  float* O = (float*)d_out;
  float* W = O + (size_t)BB*SS*DD;   // attn_output first, then attn_weights

  cudaFuncSetAttribute(attn_fused, cudaFuncAttributeMaxDynamicSharedMemorySize,
                       SMEM_BYTES);
  dim3 grid(SS/QT, HH, BB);
  attn_fused<<<grid, 128, SMEM_BYTES>>>(Q, K, V, M, O, W);
}

// round 3
// speedup vs baseline: 1.0028x; 1.0028x over previous
#include <cuda_runtime.h>
#include <cstdint>
#include <cstddef>

// Problem constants
#define BB 2
#define HH 16
#define SS 2048
#define DD 2048
#define HD 128
#define QT 64              // q rows per block
#define KT 64              // kv rows per tile
#define NT (SS/KT)         // 32 tiles
#define NWARP 4

// Padded smem strides (in floats) chosen for conflict-free fragment loads
#define KSTR 132
#define VSTR 136
#define PSTR 68

#define SM_K (KT*KSTR)
#define SM_V (KT*VSTR)
#define SM_P (NWARP*16*PSTR)
#define SM_M KT
#define SMEM_FLOATS (SM_K + SM_V + SM_P + SM_M)
#define SMEM_BYTES (SMEM_FLOATS*4)

__device__ __forceinline__ unsigned f2tf(float x){
  unsigned r; asm("cvt.rna.tf32.f32 %0, %1;" : "=r"(r) : "f"(x)); return r;
}

__device__ __forceinline__ void mma8(float&c0,float&c1,float&c2,float&c3,
    unsigned a0,unsigned a1,unsigned a2,unsigned a3,unsigned b0,unsigned b1){
  asm volatile("mma.sync.aligned.m16n8k8.row.col.f32.tf32.tf32.f32 "
    "{%0,%1,%2,%3}, {%4,%5,%6,%7}, {%8,%9}, {%0,%1,%2,%3};"
    : "+f"(c0),"+f"(c1),"+f"(c2),"+f"(c3)
    : "r"(a0),"r"(a1),"r"(a2),"r"(a3),"r"(b0),"r"(b1));
}

// Load one 64x128 K tile into SMEM as tf32 with pair-permuted columns:
// element (r, k) stored at r*KSTR + (k&~7) + (k&3)*2 + ((k>>2)&1).
// This makes the mma B-fragment pair (k, k+4) contiguous -> single LDS.64.
__device__ __forceinline__ void load_k_tile(unsigned* KsmU, const float* Kb,
                                            int t, int tid){
  for (int ci = tid; ci < KT*16; ci += 128){
    int r  = ci >> 4;
    int cb = (ci & 15) * 8;
    const float* src = Kb + (size_t)(t*KT + r)*DD + cb;
    float4 lo = *(const float4*)src;
    float4 hi = *(const float4*)(src + 4);
    unsigned* d = KsmU + r*KSTR + cb;
    ((uint4*)d)[0] = make_uint4(f2tf(lo.x), f2tf(hi.x), f2tf(lo.y), f2tf(hi.y));
    ((uint4*)d)[1] = make_uint4(f2tf(lo.z), f2tf(hi.z), f2tf(lo.w), f2tf(hi.w));
  }
}

__global__ __launch_bounds__(128, 2)
void attn_fused(const float* __restrict__ Q, const float* __restrict__ K,
                const float* __restrict__ V, const float* __restrict__ Msk,
                float* __restrict__ O, float* __restrict__ W)
{
  extern __shared__ float smem[];
  float* Ksm = smem;
  float* Vsm = Ksm + SM_K;
  float* Psm = Vsm + SM_V;
  float* msm = Psm + SM_P;
  unsigned* KsmU = (unsigned*)Ksm;
  unsigned* VsmU = (unsigned*)Vsm;

  const int tid  = threadIdx.x;
  const int warp = tid >> 5, lane = tid & 31;
  const int g = lane >> 2, q4 = lane & 3;
  const int b = blockIdx.z, h = blockIdx.y, qt = blockIdx.x;
  const int q0 = qt*QT + warp*16;

  const float* Qb = Q + ((size_t)b*SS)*DD + (size_t)h*HD;
  const float* Kb = K + ((size_t)b*SS)*DD + (size_t)h*HD;
  const float* Vb = V + ((size_t)b*SS)*DD + (size_t)h*HD;
  const float* Mb = Msk + (size_t)b*SS;

  const float scale = 0.08838834764831845f;  // 1/sqrt(128)

  // Q fragments cached in registers (tf32), rows q0+g and q0+g+8
  unsigned qr[16][4];
  {
    const float* r0 = Qb + (size_t)(q0+g)*DD;
    const float* r1 = Qb + (size_t)(q0+g+8)*DD;
#pragma unroll
    for (int kk=0; kk<16; kk++){
      qr[kk][0] = f2tf(r0[kk*8 + q4]);
      qr[kk][1] = f2tf(r1[kk*8 + q4]);
      qr[kk][2] = f2tf(r0[kk*8 + 4 + q4]);
      qr[kk][3] = f2tf(r1[kk*8 + 4 + q4]);
    }
  }

  float m0=-1e30f, m1=-1e30f, l0=0.f, l1=0.f;

  // ---------------- pass A: softmax row stats (online max / sumexp) ----------------
  for (int t=0; t<NT; t++){
    __syncthreads();
    load_k_tile(KsmU, Kb, t, tid);
    if (tid < KT) msm[tid] = Mb[t*KT + tid];
    __syncthreads();

    float s[8][4];
#pragma unroll
    for (int j=0;j<8;j++){ s[j][0]=0.f;s[j][1]=0.f;s[j][2]=0.f;s[j][3]=0.f; }
#pragma unroll
    for (int kk=0; kk<16; kk++){
#pragma unroll
      for (int j=0;j<8;j++){
        uint2 bb = *(const uint2*)(KsmU + (j*8+g)*KSTR + kk*8 + q4*2);
        mma8(s[j][0],s[j][1],s[j][2],s[j][3],
             qr[kk][0],qr[kk][1],qr[kk][2],qr[kk][3], bb.x, bb.y);
      }
    }
    float tm0=-1e30f, tm1=-1e30f;
#pragma unroll
    for (int j=0;j<8;j++){
      float mk0 = msm[j*8 + 2*q4], mk1 = msm[j*8 + 2*q4 + 1];
      s[j][0] = fmaf(s[j][0], scale, mk0);
      s[j][1] = fmaf(s[j][1], scale, mk1);
      s[j][2] = fmaf(s[j][2], scale, mk0);
      s[j][3] = fmaf(s[j][3], scale, mk1);
      tm0 = fmaxf(tm0, fmaxf(s[j][0], s[j][1]));
      tm1 = fmaxf(tm1, fmaxf(s[j][2], s[j][3]));
    }
    tm0 = fmaxf(tm0, __shfl_xor_sync(0xffffffffu, tm0, 1));
    tm0 = fmaxf(tm0, __shfl_xor_sync(0xffffffffu, tm0, 2));
    tm1 = fmaxf(tm1, __shfl_xor_sync(0xffffffffu, tm1, 1));
    tm1 = fmaxf(tm1, __shfl_xor_sync(0xffffffffu, tm1, 2));
    float nm0 = fmaxf(m0, tm0), nm1 = fmaxf(m1, tm1);
    float sm0=0.f, sm1=0.f;
#pragma unroll
    for (int j=0;j<8;j++){
      sm0 += __expf(s[j][0]-nm0) + __expf(s[j][1]-nm0);
      sm1 += __expf(s[j][2]-nm1) + __expf(s[j][3]-nm1);
    }
    sm0 += __shfl_xor_sync(0xffffffffu, sm0, 1);
    sm0 += __shfl_xor_sync(0xffffffffu, sm0, 2);
    sm1 += __shfl_xor_sync(0xffffffffu, sm1, 1);
    sm1 += __shfl_xor_sync(0xffffffffu, sm1, 2);
    l0 = l0*__expf(m0-nm0) + sm0;
    l1 = l1*__expf(m1-nm1) + sm1;
    m0 = nm0; m1 = nm1;
  }
  const float il0 = 1.f/l0, il1 = 1.f/l1;

  // ---------------- pass B: recompute scores, emit weights, PV ----------------
  float o[16][4];
#pragma unroll
  for (int j=0;j<16;j++){ o[j][0]=0.f;o[j][1]=0.f;o[j][2]=0.f;o[j][3]=0.f; }

  float* wr0 = W + (((size_t)(b*HH+h))*SS + (size_t)(q0+g))*SS;
  float* wr1 = W + (((size_t)(b*HH+h))*SS + (size_t)(q0+g+8))*SS;
  unsigned* pw = (unsigned*)Psm + warp*16*PSTR;

  for (int t=0; t<NT; t++){
    __syncthreads();
    load_k_tile(KsmU, Kb, t, tid);
    // V tile, plain layout, tf32
    for (int i=tid; i<KT*32; i+=128){
      int r = i>>5, c = (i&31)*4;
      float4 v = *(const float4*)(Vb + (size_t)(t*KT + r)*DD + c);
      ((uint4*)(VsmU + r*VSTR + c))[0] =
          make_uint4(f2tf(v.x), f2tf(v.y), f2tf(v.z), f2tf(v.w));
    }
    if (tid < KT) msm[tid] = Mb[t*KT + tid];
    __syncthreads();

    float s[8][4];
#pragma unroll
    for (int j=0;j<8;j++){ s[j][0]=0.f;s[j][1]=0.f;s[j][2]=0.f;s[j][3]=0.f; }
#pragma unroll
    for (int kk=0; kk<16; kk++){
#pragma unroll
      for (int j=0;j<8;j++){
        uint2 bb = *(const uint2*)(KsmU + (j*8+g)*KSTR + kk*8 + q4*2);
        mma8(s[j][0],s[j][1],s[j][2],s[j][3],
             qr[kk][0],qr[kk][1],qr[kk][2],qr[kk][3], bb.x, bb.y);
      }
    }

#pragma unroll
    for (int j=0;j<8;j++){
      float mk0 = msm[j*8 + 2*q4], mk1 = msm[j*8 + 2*q4 + 1];
      float p0 = __expf(fmaf(s[j][0], scale, mk0) - m0) * il0;
      float p1 = __expf(fmaf(s[j][1], scale, mk1) - m0) * il0;
      float p2 = __expf(fmaf(s[j][2], scale, mk0) - m1) * il1;
      float p3 = __expf(fmaf(s[j][3], scale, mk1) - m1) * il1;
      int col = j*8 + 2*q4;
      *(float2*)(wr0 + (size_t)t*KT + col) = make_float2(p0, p1);
      *(float2*)(wr1 + (size_t)t*KT + col) = make_float2(p2, p3);
      pw[g*PSTR + col]       = f2tf(p0);
      pw[g*PSTR + col + 1]   = f2tf(p1);
      pw[(g+8)*PSTR + col]   = f2tf(p2);
      pw[(g+8)*PSTR + col+1] = f2tf(p3);
    }
    __syncwarp();

    // PV: O(16x128) += P(16x64) @ V(64x128)
#pragma unroll
    for (int kk=0; kk<8; kk++){
      unsigned a0 = pw[g*PSTR     + kk*8 + q4];
      unsigned a1 = pw[(g+8)*PSTR + kk*8 + q4];
      unsigned a2 = pw[g*PSTR     + kk*8 + 4 + q4];
      unsigned a3 = pw[(g+8)*PSTR + kk*8 + 4 + q4];
#pragma unroll
      for (int j=0;j<16;j++){
        unsigned b0 = VsmU[(kk*8 + q4)*VSTR     + j*8 + g];
        unsigned b1 = VsmU[(kk*8 + 4 + q4)*VSTR + j*8 + g];
        mma8(o[j][0],o[j][1],o[j][2],o[j][3], a0,a1,a2,a3, b0,b1);
      }
    }
  }

  // epilogue: write attn_output [B, S, D] with head h at columns h*HD
  float* or0 = O + ((size_t)b*SS + (size_t)(q0+g))*DD + (size_t)h*HD;
  float* or1 = O + ((size_t)b*SS + (size_t)(q0+g+8))*DD + (size_t)h*HD;
#pragma unroll
  for (int j=0;j<16;j++){
    int col = j*8 + 2*q4;
    *(float2*)(or0 + col) = make_float2(o[j][0], o[j][1]);
    *(float2*)(or1 + col) = make_float2(o[j][2], o[j][3]);
  }
}

extern "C" void kernel_launch(void* const* d_in, const int* in_sizes, int n_in,
                              void* d_out, int out_size) {
  const float* Q = (const float*)d_in[0];
  const float* K = (const float*)d_in[1];
  const float* V = (const float*)d_in[2];
  const float* M = (const float*)d_in[3];
  float* O = (float*)d_out;
  float* W = O + (size_t)BB*SS*DD;   // attn_output first, then attn_weights

  cudaFuncSetAttribute(attn_fused, cudaFuncAttributeMaxDynamicSharedMemorySize,
                       SMEM_BYTES);
  dim3 grid(SS/QT, HH, BB);
  attn_fused<<<grid, 128, SMEM_BYTES>>>(Q, K, V, M, O, W);
}